// round 13
// baseline (speedup 1.0000x reference)
#include <cuda_runtime.h>
#include <math.h>

#define NMAX 4096
#define FMAX 1024
#define IMGF 256.0f
#define SIGMA 3e-05f
#define INV_SIGMA (1.0f / SIGMA)
#define D_HI (17.4f * SIGMA)     // d above this: sigmoid(d/sigma) == 1.0f -> covered
#define D_LO (-30.0f * SIGMA)    // d below this: contribution < 1e-13 -> skip

#define NBLK 256            // 16x16 tiles of 16x16 pixels
#define TPB  1024           // 4 threads (lane-grouped) per pixel

// Scratch (no allocations allowed in kernel_launch)
__device__ float4 g_f0[FMAX];   // A0,B0,C0,A1
__device__ float4 g_f1[FMAX];   // B1,C1,A2,B2
__device__ float  g_f2[FMAX];   // C2
__device__ float  g_partial[NBLK];
__device__ unsigned g_ticket = 0;

// ---------------- Kernel 1: fully parallel per-face prep ----------------
__device__ __forceinline__ float2 project_one(const float* __restrict__ verts, int i,
                                              const float* __restrict__ K,
                                              const float* __restrict__ R,
                                              const float* __restrict__ t) {
    float vx = verts[3 * i + 0];
    float vy = verts[3 * i + 1];
    float vz = verts[3 * i + 2];
    float p0 = R[0] * vx + R[1] * vy + R[2] * vz + t[0];
    float p1 = R[3] * vx + R[4] * vy + R[5] * vz + t[1];
    float p2 = R[6] * vx + R[7] * vy + R[8] * vz + t[2];
    float zd = p2 + 1e-5f;
    float xn = p0 / zd;
    float yn = p1 / zd;
    float u  = K[0] * xn + K[1] * yn + K[2];
    float vv = K[3] * xn + K[4] * yn + K[5];
    vv = IMGF - vv;
    u  = 2.0f * (u  - IMGF * 0.5f) / IMGF;
    vv = 2.0f * (vv - IMGF * 0.5f) / IMGF;
    return make_float2(u, vv);
}

__global__ void __launch_bounds__(256) prep_kernel(const float* __restrict__ verts,
                                                   const float* __restrict__ K,
                                                   const float* __restrict__ R,
                                                   const float* __restrict__ t,
                                                   const int* __restrict__ faces,
                                                   int F) {
    int f = blockIdx.x * blockDim.x + threadIdx.x;
    if (f == 0) g_ticket = 0;            // replay-safe (also reset by raster last block)
    if (f >= F) return;

    int i0 = faces[3 * f + 0];
    int i1 = faces[3 * f + 1];
    int i2 = faces[3 * f + 2];
    float2 v0 = project_one(verts, i0, K, R, t);
    float2 v1 = project_one(verts, i1, K, R, t);
    float2 v2 = project_one(verts, i2, K, R, t);
    float x0 = v0.x, y0 = v0.y;
    float x1 = v1.x, y1 = v1.y;
    float x2 = v2.x, y2 = v2.y;

    float area = (x1 - x0) * (y2 - y0) - (y1 - y0) * (x2 - x0);
    float s = (area > 0.0f) ? 1.0f : ((area < 0.0f) ? -1.0f : 0.0f);

    float dx01 = x1 - x0, dy01 = y1 - y0;
    float A0 = -s * dy01;
    float B0 =  s * dx01;
    float C0 =  s * (dy01 * x0 - dx01 * y0);
    float dx12 = x2 - x1, dy12 = y2 - y1;
    float A1 = -s * dy12;
    float B1 =  s * dx12;
    float C1 =  s * (dy12 * x1 - dx12 * y1);
    float dx20 = x0 - x2, dy20 = y0 - y2;
    float A2 = -s * dy20;
    float B2 =  s * dx20;
    float C2 =  s * (dy20 * x2 - dx20 * y2);

    g_f0[f] = make_float4(A0, B0, C0, A1);
    g_f1[f] = make_float4(B1, C1, A2, B2);
    g_f2[f] = C2;
}

// ---------------- Kernel 2: tile-culled rasterize + full reduce ----------------
// 256 blocks = 16x16 tiles of 16x16 pixels. 1024 threads: lanes 4p..4p+3 share
// pixel p, each walking a quarter (stride 4) of the tile's compacted face list.
// Quad combine (covered OR, acc sum) via shfl_xor(1),(2) -> deterministic
// (fp add of 2 operands is commutative with identical rounding).
__global__ void __launch_bounds__(TPB) raster_kernel(const float* __restrict__ image_ref,
                                                     int F, float* __restrict__ out) {
    __shared__ float4   c0[FMAX];
    __shared__ float4   c1[FMAX];
    __shared__ float    c2s[FMAX];
    __shared__ unsigned gmask[32];      // one 32-face group per warp
    __shared__ int      goff[32];
    __shared__ float    wsum[32];
    __shared__ int      s_cnt;
    __shared__ int      s_allcov;
    __shared__ int      s_last;

    int tid   = threadIdx.x;
    int lane  = tid & 31;
    int wid   = tid >> 5;
    int p     = tid >> 2;               // pixel index within tile (0..255)
    int slice = tid & 3;                // face-list slice (0..3)
    int tx = blockIdx.x & 15;
    int ty = blockIdx.x >> 4;
    int col = tx * 16 + (p & 15);
    int row = ty * 16 + (p >> 4);
    int pix = row * 256 + col;

    float px =  (2.0f * (float)col + 1.0f - IMGF) * (1.0f / IMGF);
    float py = -((2.0f * (float)row + 1.0f - IMGF) * (1.0f / IMGF));

    // tile center + half extent (pixel centers span +/- 15/256 around center)
    float cx =  (2.0f * (float)(tx * 16) + 16.0f - IMGF) * (1.0f / IMGF);
    float cy = -((2.0f * (float)(ty * 16) + 16.0f - IMGF) * (1.0f / IMGF));
    const float h = 15.0f / 256.0f;

    if (tid == 0) s_allcov = 0;
    __syncthreads();

    // ---- pass 1: classify (1 face/thread, one ballot per warp) ----
    {
        int f = tid;
        bool interesting = false;
        if (f < F) {
            float4 a  = g_f0[f];
            float4 b  = g_f1[f];
            float  cc = g_f2[f];
            float w0 = fmaf(a.x, cx, fmaf(a.y, cy, a.z));
            float r0 = (fabsf(a.x) + fabsf(a.y)) * h;
            float w1 = fmaf(a.w, cx, fmaf(b.x, cy, b.y));
            float r1 = (fabsf(a.w) + fabsf(b.x)) * h;
            float w2 = fmaf(b.z, cx, fmaf(b.w, cy, cc));
            float r2 = (fabsf(b.z) + fabsf(b.w)) * h;
            float dmin = fminf(w0 - r0, fminf(w1 - r1, w2 - r2));
            float dmax = fminf(w0 + r0, fminf(w1 + r1, w2 + r2));
            if (dmin > 18.0f * SIGMA) {
                s_allcov = 1;           // face fully covers the tile
            } else if (dmax > -31.0f * SIGMA) {
                interesting = true;     // within soft band or partially covering
            }
        }
        unsigned m = __ballot_sync(0xffffffffu, interesting);
        if (lane == 0) gmask[wid] = m;
    }
    __syncthreads();

    float cov;
    if (s_allcov) {
        cov = 1.0f;                     // whole tile covered: no per-pixel loop
    } else {
        // ---- deterministic exclusive scan of 32 group popcounts (warp 0) ----
        if (tid < 32) {
            int cnt = __popc(gmask[tid]);
            int x = cnt;
            #pragma unroll
            for (int off = 1; off < 32; off <<= 1) {
                int y = __shfl_up_sync(0xffffffffu, x, off);
                if (tid >= off) x += y;
            }
            goff[tid] = x - cnt;
            if (tid == 31) s_cnt = x;
        }
        __syncthreads();

        // ---- coefficient compaction (fixed order: ascending face index) ----
        {
            unsigned m = gmask[wid];
            if (m & (1u << lane)) {
                int pos = goff[wid] + __popc(m & ((1u << lane) - 1u));
                c0[pos]  = g_f0[tid];
                c1[pos]  = g_f1[tid];
                c2s[pos] = g_f2[tid];
            }
        }
        __syncthreads();
        int cnt = s_cnt;

        // ---- per-pixel loop: this thread walks indices slice, slice+4, ...
        //      chunked 32 faces (8 per slice) with one quad-combined __all_sync.
        float acc = 0.0f;
        bool covered = false;
        int base = 0;
        for (; base + 32 <= cnt; base += 32) {
            #pragma unroll
            for (int j = 0; j < 8; ++j) {
                int idx = base + slice + 4 * j;
                float4 a  = c0[idx];
                float4 b  = c1[idx];
                float  cc = c2s[idx];
                float w0 = fmaf(a.x, px, fmaf(a.y, py, a.z));
                float w1 = fmaf(a.w, px, fmaf(b.x, py, b.y));
                float w2 = fmaf(b.z, px, fmaf(b.w, py, cc));
                float d  = fminf(w0, fminf(w1, w2));
                if (d > D_HI) {
                    covered = true;     // sigmoid == 1.0f in fp32 -> cov = 1
                } else if (d > D_LO) {
                    float tt = d * INV_SIGMA;
                    float prob = 1.0f / (1.0f + expf(-tt));
                    acc += log1pf(1e-12f - prob);
                }
            }
            // Unconditional shuffles: all 32 lanes participate.
            bool oc1 = __shfl_xor_sync(0xffffffffu, covered, 1);
            bool c01 = covered || oc1;
            bool oc2 = __shfl_xor_sync(0xffffffffu, c01, 2);
            bool quadcov = c01 || oc2;
            if (__all_sync(0xffffffffu, quadcov)) { base = cnt; break; }
        }
        for (int idx = base + slice; idx < cnt; idx += 4) {   // remainder (no sync)
            float4 a  = c0[idx];
            float4 b  = c1[idx];
            float  cc = c2s[idx];
            float w0 = fmaf(a.x, px, fmaf(a.y, py, a.z));
            float w1 = fmaf(a.w, px, fmaf(b.x, py, b.y));
            float w2 = fmaf(b.z, px, fmaf(b.w, py, cc));
            float d  = fminf(w0, fminf(w1, w2));
            if (d > D_HI) {
                covered = true;
            } else if (d > D_LO) {
                float tt = d * INV_SIGMA;
                float prob = 1.0f / (1.0f + expf(-tt));
                acc += log1pf(1e-12f - prob);
            }
        }

        // ---- quad combine (unconditional shuffles; fp add commutative ->
        //      all four lanes get bit-identical sums; deterministic) ----
        bool  oc1 = __shfl_xor_sync(0xffffffffu, covered, 1);
        float oa1 = __shfl_xor_sync(0xffffffffu, acc, 1);
        covered = covered || oc1;
        acc += oa1;
        bool  oc2 = __shfl_xor_sync(0xffffffffu, covered, 2);
        float oa2 = __shfl_xor_sync(0xffffffffu, acc, 2);
        covered = covered || oc2;
        acc += oa2;
        cov = covered ? 1.0f : (1.0f - expf(acc));
    }

    // ---- block reduction of squared error (slice==0 lanes carry pixels) ----
    float v = 0.0f;
    if (slice == 0) {
        float df = cov - image_ref[pix];
        v = df * df;
    }
    #pragma unroll
    for (int off = 16; off > 0; off >>= 1)
        v += __shfl_down_sync(0xffffffffu, v, off);
    if (lane == 0) wsum[wid] = v;
    __syncthreads();
    if (tid == 0) {
        float bs = 0.0f;
        #pragma unroll
        for (int w = 0; w < 32; ++w) bs += wsum[w];
        g_partial[blockIdx.x] = bs;
        __threadfence();
        unsigned tkt = atomicAdd(&g_ticket, 1u);
        s_last = (tkt == gridDim.x - 1) ? 1 : 0;
    }
    __syncthreads();

    // ---- last block performs the deterministic final reduction ----
    if (s_last) {
        __threadfence();
        float sv = (tid < NBLK) ? g_partial[tid] : 0.0f;
        #pragma unroll
        for (int off = 16; off > 0; off >>= 1)
            sv += __shfl_down_sync(0xffffffffu, sv, off);
        if (lane == 0) wsum[wid] = sv;
        __syncthreads();
        if (tid == 0) {
            float tot = 0.0f;
            #pragma unroll
            for (int w = 0; w < 32; ++w) tot += wsum[w];
            out[0] = tot;
            g_ticket = 0;               // reset for next graph replay
        }
    }
}

extern "C" void kernel_launch(void* const* d_in, const int* in_sizes, int n_in,
                              void* d_out, int out_size) {
    const float* verts     = (const float*)d_in[0];  // (1,N,3)
    const float* K         = (const float*)d_in[1];  // (1,3,3)
    const float* R         = (const float*)d_in[2];  // (1,3,3)
    const float* t         = (const float*)d_in[3];  // (1,3)
    const float* image_ref = (const float*)d_in[4];  // (256,256)
    const int*   faces     = (const int*)d_in[5];    // (1,F,3)
    float* out = (float*)d_out;

    int F = in_sizes[5] / 3;
    if (F > FMAX) F = FMAX;

    prep_kernel<<<(F + 255) / 256, 256>>>(verts, K, R, t, faces, F);
    raster_kernel<<<NBLK, TPB>>>(image_ref, F, out);
}